// round 2
// baseline (speedup 1.0000x reference)
#include <cuda_runtime.h>
#include <math.h>

#define S_LEN 4096
#define B_DIM 32
#define H_DIM 512

// ---------------- packed fp32x2 helpers (Blackwell FFMA2 path) ----------------
__device__ __forceinline__ unsigned long long pk2(float x, float y) {
    unsigned long long r;
    asm("mov.b64 %0, {%1, %2};" : "=l"(r) : "f"(x), "f"(y));
    return r;
}
__device__ __forceinline__ void fma2(unsigned long long &d, unsigned long long a, unsigned long long b) {
    asm("fma.rn.f32x2 %0, %1, %2, %0;" : "+l"(d) : "l"(a), "l"(b));
}
__device__ __forceinline__ float2 up2(unsigned long long v) {
    float2 r;
    asm("mov.b64 {%0, %1}, %2;" : "=f"(r.x), "=f"(r.y) : "l"(v));
    return r;
}

// ---------------- kernel 1: fused GEMM-bilinear -> logits ----------------
// e[r] = sum_k ( sum_h Enc[r-32,h] * W[h,k] ) * Enc[r,k] * hid[r&31,k]
// GEMM tile: 128 rows x 128 W-cols x K=512, 4 col-tiles looped per CTA,
// epilogue reduces each row tile against Enc[r,:]*hid[b,:] (no C writeback).
constexpr int BM = 128;
constexpr int BN = 128;
constexpr int BK = 16;
constexpr int AST = 132;   // padded stride: 2-way-max STS conflicts, 16B-aligned rows

__global__ __launch_bounds__(256) void bilinear_logits(
    const float* __restrict__ enc, const float* __restrict__ hid,
    const float* __restrict__ Wm, float* __restrict__ logits)
{
    __shared__ float As[2][BK][AST];
    __shared__ float Bs[2][BK][BN];

    const int tid = threadIdx.x;
    const int rm = tid >> 4;     // 0..15  (row group of 8)
    const int cn = tid & 15;     // 0..15  (col group of 8)
    const int row0 = blockIdx.x * BM;

    // A-tile slot mapping: slots tid and tid+256 over 512 float4 slots (128x16)
    const int aRow0 = tid >> 2;
    const int aRow1 = aRow0 + 64;
    const int aC    = (tid & 3) * 4;
    const long xr0 = max(row0 + aRow0 - B_DIM, 0);
    const long xr1 = max(row0 + aRow1 - B_DIM, 0);
    // B-tile slot mapping: 16x128 floats; rows tid>>5 and tid>>5 + 8
    const int bRow = tid >> 5;
    const int bCol = (tid & 31) * 4;

    float rowacc[8];
#pragma unroll
    for (int i = 0; i < 8; ++i) rowacc[i] = 0.f;

    for (int nt = 0; nt < 4; ++nt) {
        const int nbase = nt * BN;
        unsigned long long c[8][4];
#pragma unroll
        for (int i = 0; i < 8; ++i)
#pragma unroll
            for (int j = 0; j < 4; ++j) c[i][j] = 0ull;

        float4 av0, av1, bv0, bv1;
        // prologue: stage 0 -> buf 0
        av0 = *(const float4*)(enc + xr0 * H_DIM + aC);
        av1 = *(const float4*)(enc + xr1 * H_DIM + aC);
        bv0 = *(const float4*)(Wm + (size_t)bRow * H_DIM + nbase + bCol);
        bv1 = *(const float4*)(Wm + (size_t)(bRow + 8) * H_DIM + nbase + bCol);
        As[0][aC+0][aRow0] = av0.x; As[0][aC+1][aRow0] = av0.y;
        As[0][aC+2][aRow0] = av0.z; As[0][aC+3][aRow0] = av0.w;
        As[0][aC+0][aRow1] = av1.x; As[0][aC+1][aRow1] = av1.y;
        As[0][aC+2][aRow1] = av1.z; As[0][aC+3][aRow1] = av1.w;
        *(float4*)&Bs[0][bRow][bCol]     = bv0;
        *(float4*)&Bs[0][bRow + 8][bCol] = bv1;
        __syncthreads();

#pragma unroll 1
        for (int st = 0; st < 32; ++st) {
            const int buf = st & 1;
            if (st < 31) {
                const int kb = (st + 1) * BK;
                av0 = *(const float4*)(enc + xr0 * H_DIM + kb + aC);
                av1 = *(const float4*)(enc + xr1 * H_DIM + kb + aC);
                bv0 = *(const float4*)(Wm + (size_t)(kb + bRow) * H_DIM + nbase + bCol);
                bv1 = *(const float4*)(Wm + (size_t)(kb + bRow + 8) * H_DIM + nbase + bCol);
            }
#pragma unroll
            for (int kk = 0; kk < BK; ++kk) {
                const float4 a0 = *(const float4*)&As[buf][kk][rm * 8];
                const float4 a1 = *(const float4*)&As[buf][kk][rm * 8 + 4];
                const ulonglong2 b0 = *(const ulonglong2*)&Bs[buf][kk][cn * 8];
                const ulonglong2 b1 = *(const ulonglong2*)&Bs[buf][kk][cn * 8 + 4];
                const float a_[8] = {a0.x, a0.y, a0.z, a0.w, a1.x, a1.y, a1.z, a1.w};
#pragma unroll
                for (int i = 0; i < 8; ++i) {
                    const unsigned long long ad = pk2(a_[i], a_[i]);
                    fma2(c[i][0], ad, b0.x);
                    fma2(c[i][1], ad, b0.y);
                    fma2(c[i][2], ad, b1.x);
                    fma2(c[i][3], ad, b1.y);
                }
            }
            if (st < 31) {
                const int nb = buf ^ 1;
                As[nb][aC+0][aRow0] = av0.x; As[nb][aC+1][aRow0] = av0.y;
                As[nb][aC+2][aRow0] = av0.z; As[nb][aC+3][aRow0] = av0.w;
                As[nb][aC+0][aRow1] = av1.x; As[nb][aC+1][aRow1] = av1.y;
                As[nb][aC+2][aRow1] = av1.z; As[nb][aC+3][aRow1] = av1.w;
                *(float4*)&Bs[nb][bRow][bCol]     = bv0;
                *(float4*)&Bs[nb][bRow + 8][bCol] = bv1;
            }
            __syncthreads();
        }

        // fused epilogue: per-row partial dot with Enc[r,:]*hid[b,:], reduce 16 col-lanes
#pragma unroll
        for (int i = 0; i < 8; ++i) {
            const long rg = row0 + rm * 8 + i;
            const float* er = enc + rg * H_DIM + nbase + cn * 8;
            const float* hr = hid + (size_t)(rg & 31) * H_DIM + nbase + cn * 8;
            const float4 e0 = *(const float4*)er;
            const float4 e1 = *(const float4*)(er + 4);
            const float4 h0 = *(const float4*)hr;
            const float4 h1 = *(const float4*)(hr + 4);
            const float2 c0 = up2(c[i][0]), c1 = up2(c[i][1]);
            const float2 c2 = up2(c[i][2]), c3 = up2(c[i][3]);
            float s = c0.x * e0.x * h0.x + c0.y * e0.y * h0.y
                    + c1.x * e0.z * h0.z + c1.y * e0.w * h0.w
                    + c2.x * e1.x * h1.x + c2.y * e1.y * h1.y
                    + c3.x * e1.z * h1.z + c3.y * e1.w * h1.w;
            s += __shfl_xor_sync(0xffffffffu, s, 8);
            s += __shfl_xor_sync(0xffffffffu, s, 4);
            s += __shfl_xor_sync(0xffffffffu, s, 2);
            s += __shfl_xor_sync(0xffffffffu, s, 1);
            rowacc[i] += s;   // valid on cn==0 lanes
        }
    }

    if (cn == 0) {
#pragma unroll
        for (int i = 0; i < 8; ++i) {
            const int rg = row0 + rm * 8 + i;
            // r = s*32 + b  ->  out[b*4096 + s]
            logits[(rg & 31) * S_LEN + (rg >> 5)] = rowacc[i];
        }
    }
}

// ---------------- kernel 2: affect term + s==0 fixup + softmax ----------------
__global__ __launch_bounds__(256) void softmax_finalize(
    const float* __restrict__ enc, const float* __restrict__ hid,
    const float* __restrict__ emb, const float* __restrict__ aff,
    float* __restrict__ out)
{
    const int b = blockIdx.x;
    const int tid = threadIdx.x;
    const int lane = tid & 31, wid = tid >> 5;
    __shared__ float red[8][4];
    __shared__ float fin[4];
    __shared__ float rmax[8];
    __shared__ float rsum[8];

    // a[k] = hid[b,:] . affect[:,k];  e0 = hid[b,:] . enc[0,b,:]
    float a0 = 0.f, a1 = 0.f, a2 = 0.f, e0 = 0.f;
    for (int h = tid; h < H_DIM; h += 256) {
        const float hv = hid[b * H_DIM + h];
        a0 += hv * aff[h * 3 + 0];
        a1 += hv * aff[h * 3 + 1];
        a2 += hv * aff[h * 3 + 2];
        e0 += hv * enc[b * H_DIM + h];   // row (s=0,b)
    }
#pragma unroll
    for (int m = 16; m; m >>= 1) {
        a0 += __shfl_xor_sync(~0u, a0, m);
        a1 += __shfl_xor_sync(~0u, a1, m);
        a2 += __shfl_xor_sync(~0u, a2, m);
        e0 += __shfl_xor_sync(~0u, e0, m);
    }
    if (lane == 0) { red[wid][0] = a0; red[wid][1] = a1; red[wid][2] = a2; red[wid][3] = e0; }
    __syncthreads();
    if (tid < 4) {
        float s = 0.f;
        for (int w = 0; w < 8; ++w) s += red[w][tid];
        fin[tid] = s;
    }
    __syncthreads();
    const float A0 = fin[0], A1 = fin[1], A2 = fin[2], E0 = fin[3];

    float l[16];
    float mx = -INFINITY;
#pragma unroll
    for (int it = 0; it < 16; ++it) {
        const int s = tid + it * 256;
        float v = (s == 0) ? E0 : out[b * S_LEN + s];
        const float* ep = emb + ((size_t)s * B_DIM + b) * 3;
        v += A0 * ep[0] + A1 * ep[1] + A2 * ep[2];
        l[it] = v;
        mx = fmaxf(mx, v);
    }
#pragma unroll
    for (int m = 16; m; m >>= 1) mx = fmaxf(mx, __shfl_xor_sync(~0u, mx, m));
    if (lane == 0) rmax[wid] = mx;
    __syncthreads();
    if (tid == 0) {
        float m2 = rmax[0];
        for (int w = 1; w < 8; ++w) m2 = fmaxf(m2, rmax[w]);
        rmax[0] = m2;
    }
    __syncthreads();
    const float MX = rmax[0];

    float sum = 0.f;
#pragma unroll
    for (int it = 0; it < 16; ++it) { l[it] = expf(l[it] - MX); sum += l[it]; }
#pragma unroll
    for (int m = 16; m; m >>= 1) sum += __shfl_xor_sync(~0u, sum, m);
    if (lane == 0) rsum[wid] = sum;
    __syncthreads();
    if (tid == 0) {
        float s2 = 0.f;
        for (int w = 0; w < 8; ++w) s2 += rsum[w];
        rsum[0] = s2;
    }
    __syncthreads();
    const float inv = 1.0f / rsum[0];
#pragma unroll
    for (int it = 0; it < 16; ++it)
        out[b * S_LEN + tid + it * 256] = l[it] * inv;
}

// ---------------- launch ----------------
extern "C" void kernel_launch(void* const* d_in, const int* in_sizes, int n_in,
                              void* d_out, int out_size) {
    const float *hid = nullptr, *enc = nullptr, *emb = nullptr, *Wm = nullptr, *aff = nullptr;
    for (int i = 0; i < n_in; ++i) {
        switch (in_sizes[i]) {
            case 16384:    hid = (const float*)d_in[i]; break;  // hidden [1,32,512]
            case 67108864: enc = (const float*)d_in[i]; break;  // encoder_outputs [4096,32,512]
            case 393216:   emb = (const float*)d_in[i]; break;  // embedding [4096,32,3]
            case 262144:   Wm  = (const float*)d_in[i]; break;  // bigram_matrix [512,512]
            case 1536:     aff = (const float*)d_in[i]; break;  // affect_matrix [512,3]
        }
    }
    float* out = (float*)d_out;  // [32,1,4096] fp32; used as logit scratch by kernel 1

    bilinear_logits<<<(S_LEN * B_DIM) / BM, 256>>>(enc, hid, Wm, out);
    softmax_finalize<<<B_DIM, 256>>>(enc, hid, emb, aff, out);
}